// round 13
// baseline (speedup 1.0000x reference)
#include <cuda_runtime.h>
#include <cuda_pipeline.h>

static constexpr int H = 512;
static constexpr int W = 512;
static constexpr unsigned FULL = 0xFFFFFFFFu;
static constexpr int NQ = 8;      // quads (4 output rows) per warp strip
static constexpr int RS = 264;    // smem row stride in floats (16B-aligned rows)
static constexpr int D0 = 4;      // first data column in a smem row
static constexpr int EL = 3;      // left-halo float index
static constexpr int ER = 260;    // right-halo float index

__device__ __forceinline__ float med3f(float a, float b, float c) {
    return fmaxf(fminf(a, b), fminf(fmaxf(a, b), c));
}

// Horizontal merge for 8 outputs of one row. lo/md/hi: [L-edge, 8 own, R-edge].
__device__ __forceinline__ void hmerge8(const float* lo, const float* md,
                                         const float* hi, float* o) {
#pragma unroll
    for (int k = 0; k < 4; k++) {
        float pxl = fmaxf(lo[2 * k + 1], lo[2 * k + 2]);
        float pzl = fminf(hi[2 * k + 1], hi[2 * k + 2]);
        float mn  = fminf(md[2 * k + 1], md[2 * k + 2]);
        float mx  = fmaxf(md[2 * k + 1], md[2 * k + 2]);
        float X0 = fmaxf(lo[2 * k], pxl);
        float X1 = fmaxf(pxl, lo[2 * k + 3]);
        float Z0 = fminf(hi[2 * k], pzl);
        float Z1 = fminf(pzl, hi[2 * k + 3]);
        float Y0 = fmaxf(mn, fminf(mx, md[2 * k]));
        float Y1 = fmaxf(mn, fminf(mx, md[2 * k + 3]));
        o[2 * k]     = med3f(X0, Y0, Z0);
        o[2 * k + 1] = med3f(X1, Y1, Z1);
    }
}

// Merge row t into pre-sorted pair (p,q), exchange edge triples, merge, store one row.
__device__ __forceinline__ void do_row(const float* t, const float* p, const float* q,
                                        float et, float ep, float eq,
                                        bool isL, bool isR,
                                        float* __restrict__ orow, int c0) {
    float lo[10], md[10], hi[10];
#pragma unroll
    for (int i = 0; i < 8; i++) {
        float m = fmaxf(t[i], p[i]);
        lo[i + 1] = fminf(t[i], p[i]);
        hi[i + 1] = fmaxf(m, q[i]);
        md[i + 1] = fminf(m, q[i]);
    }
    float em = fmaxf(et, ep);
    float elo = fminf(et, ep), ehi = fmaxf(em, eq), emd = fminf(em, eq);
    float Ll = __shfl_up_sync(FULL, lo[8], 1);
    float Lm = __shfl_up_sync(FULL, md[8], 1);
    float Lh = __shfl_up_sync(FULL, hi[8], 1);
    float Rl = __shfl_down_sync(FULL, lo[1], 1);
    float Rm = __shfl_down_sync(FULL, md[1], 1);
    float Rh = __shfl_down_sync(FULL, hi[1], 1);
    lo[0] = isL ? elo : Ll;  md[0] = isL ? emd : Lm;  hi[0] = isL ? ehi : Lh;
    lo[9] = isR ? elo : Rl;  md[9] = isR ? emd : Rm;  hi[9] = isR ? ehi : Rh;
    float o[8];
    hmerge8(lo, md, hi, o);
    *(float4*)(orow + c0)     = make_float4(o[0], o[1], o[2], o[3]);
    *(float4*)(orow + c0 + 4) = make_float4(o[4], o[5], o[6], o[7]);
}

__global__ __launch_bounds__(64, 8)
void median3x3_kernel(const float* __restrict__ in, float* __restrict__ out, int nimg) {
    // Per-warp double buffer: [warp][buf][row][RS]. 2*2*6*264*4B = 25.3 KB/CTA.
    __shared__ __align__(16) float sbuf[2][2][6][RS];

    const int lane = threadIdx.x & 31;
    const int w = threadIdx.x >> 5;
    const int gwarp = blockIdx.x * 2 + w;

    // Strip = (img, column half, quad-group of NQ vertical quads).
    const int img = gwarp >> 5;                 // 32 strips per image
    if (img >= nimg) return;
    const int rem = gwarp & 31;
    const int c0s = (rem & 1) << 8;             // strip column base: 0 or 256
    const int ybase = (rem >> 1) * (4 * NQ);    // 16 quad-groups x 32 rows

    const float* __restrict__ base = in + (size_t)img * (H * W);
    float* __restrict__ obase = out + (size_t)img * (H * W);

    const bool isL = (lane == 0);
    const bool isR = (lane == 31);
    const int ci = D0 + 8 * lane;
    const int eidx = isL ? EL : ER;             // lanes 1..30 broadcast-read ER (unused)

    float (*buf)[6][RS] = sbuf[w];

    // Stage input rows y0-1..y0+4 of this strip into dst via cp.async.
    auto stage = [&](float dst[6][RS], int y0) {
#pragma unroll
        for (int r = 0; r < 6; r++) {
            const int gy = y0 - 1 + r;
            float* drow = dst[r];
            if ((unsigned)gy < (unsigned)H) {
                const float* srow = base + gy * W + c0s;
                __pipeline_memcpy_async(&drow[ci],     srow + 8 * lane,     16);
                __pipeline_memcpy_async(&drow[ci + 4], srow + 8 * lane + 4, 16);
                if (isL) {
                    if (c0s > 0) __pipeline_memcpy_async(&drow[EL], srow - 1, 4);
                    else drow[EL] = 0.f;
                }
                if (isR) {
                    if (c0s + 256 < W) __pipeline_memcpy_async(&drow[ER], srow + 256, 4);
                    else drow[ER] = 0.f;
                }
            } else {
                *(float4*)&drow[ci]     = make_float4(0.f, 0.f, 0.f, 0.f);
                *(float4*)&drow[ci + 4] = make_float4(0.f, 0.f, 0.f, 0.f);
                if (isL) drow[EL] = 0.f;
                if (isR) drow[ER] = 0.f;
            }
        }
    };

    // R5 compute network, fed from smem.
    auto compute = [&](const float (*brow)[RS], int y0) {
        float4 v[12];
        float e[6];
#pragma unroll
        for (int k = 0; k < 6; k++) {
            v[2 * k]     = *(const float4*)&brow[k][ci];
            v[2 * k + 1] = *(const float4*)&brow[k][ci + 4];
            e[k] = brow[k][eidx];
        }
        const int c0 = c0s + 8 * lane;

        float r2[8] = {v[4].x, v[4].y, v[4].z, v[4].w, v[5].x, v[5].y, v[5].z, v[5].w};
        float r3[8] = {v[6].x, v[6].y, v[6].z, v[6].w, v[7].x, v[7].y, v[7].z, v[7].w};
        float p[8], q[8];
        {
            float r1[8] = {v[2].x, v[2].y, v[2].z, v[2].w, v[3].x, v[3].y, v[3].z, v[3].w};
#pragma unroll
            for (int i = 0; i < 8; i++) {
                p[i] = fminf(r1[i], r2[i]);
                q[i] = fmaxf(r1[i], r2[i]);
            }
        }
        {
            const float epA = fminf(e[1], e[2]), eqA = fmaxf(e[1], e[2]);
            float t0[8] = {v[0].x, v[0].y, v[0].z, v[0].w, v[1].x, v[1].y, v[1].z, v[1].w};
            do_row(t0, p, q, e[0], epA, eqA, isL, isR, obase + (y0    ) * W, c0);
            do_row(r3, p, q, e[3], epA, eqA, isL, isR, obase + (y0 + 1) * W, c0);
        }
        {
            float r4[8] = {v[8].x, v[8].y, v[8].z, v[8].w, v[9].x, v[9].y, v[9].z, v[9].w};
#pragma unroll
            for (int i = 0; i < 8; i++) {
                float mn = fminf(r3[i], r4[i]);
                float mx = fmaxf(r3[i], r4[i]);
                p[i] = mn;
                q[i] = mx;
            }
        }
        {
            const float epB = fminf(e[3], e[4]), eqB = fmaxf(e[3], e[4]);
            do_row(r2, p, q, e[2], epB, eqB, isL, isR, obase + (y0 + 2) * W, c0);
            float t5[8] = {v[10].x, v[10].y, v[10].z, v[10].w, v[11].x, v[11].y, v[11].z, v[11].w};
            do_row(t5, p, q, e[5], epB, eqB, isL, isR, obase + (y0 + 3) * W, c0);
        }
    };

    // Prologue: two stages in flight.
    stage(buf[0], ybase);
    __pipeline_commit();
    stage(buf[1], ybase + 4);
    __pipeline_commit();

#pragma unroll 1
    for (int iq = 0; iq < NQ; iq++) {
        __pipeline_wait_prior(1);      // stage iq complete; stage iq+1 may fly
        __syncwarp();                  // cross-lane visibility of staged data
        compute(buf[iq & 1], ybase + 4 * iq);
        __syncwarp();                  // all lanes done reading before refill
        if (iq + 2 < NQ) stage(buf[iq & 1], ybase + 4 * (iq + 2));
        __pipeline_commit();           // commit unconditionally: group count stays aligned
    }
}

extern "C" void kernel_launch(void* const* d_in, const int* in_sizes, int n_in,
                              void* d_out, int out_size) {
    const float* x = (const float*)d_in[0];
    float* y = (float*)d_out;
    const int nimg = in_sizes[0] / (H * W);   // B*C images
    const int warps = nimg * 32;              // 2 halves x 16 quad-groups per image
    const int grid = warps / 2;               // 2 warps per CTA
    median3x3_kernel<<<grid, 64>>>(x, y, nimg);
}